// round 1
// baseline (speedup 1.0000x reference)
#include <cuda_runtime.h>
#include <cuda_bf16.h>
#include <cstdint>

#define NN 50000
#define NE 800000
#define CH 128

// ---------------- scratch (no allocations allowed) ----------------
__device__ float g_deg[NN];
__device__ float g_dinv[NN];
__device__ float g_bufA[(size_t)NN * CH];
__device__ float g_bufB[(size_t)NN * CH];
__device__ int   g_is64;

// ---------------- edge-index dtype sniff ----------------
// If edge_index is int64 (little-endian, values < 2^31), every odd 32-bit word
// of the buffer is 0. If it is int32, odd words are random indices in
// [0, 50000) and are essentially never all zero.
__global__ void k_detect(const int* __restrict__ ei32) {
    int z = 0;
    for (int i = 1; i < 256; i += 2)
        if (ei32[i] == 0) z++;
    g_is64 = (z > 64) ? 1 : 0;
}

__device__ __forceinline__ int edge_at(const void* __restrict__ ei, int pos) {
    if (g_is64) return (int)((const long long*)ei)[pos];
    return ((const int*)ei)[pos];
}

// ---------------- degree / normalization ----------------
__global__ void k_deg_init() {
    int i = blockIdx.x * blockDim.x + threadIdx.x;
    if (i < NN) g_deg[i] = 1.0f;   // self loop
}

__global__ void k_deg_edge(const void* __restrict__ ei) {
    int e = blockIdx.x * blockDim.x + threadIdx.x;
    if (e < NE) atomicAdd(&g_deg[edge_at(ei, e)], 1.0f);
}

__global__ void k_dinv() {
    int i = blockIdx.x * blockDim.x + threadIdx.x;
    if (i < NN) g_dinv[i] = rsqrtf(g_deg[i]);   // deg >= 1 always
}

// ---------------- aggregation ----------------
// out[i,:] = h[i,:]*dinv[i]^2 + bias  (self-loop term + bias folded in)
__global__ void k_self_bias(const float* __restrict__ hin,
                            float* __restrict__ hout,
                            const float* __restrict__ bias) {
    int idx = blockIdx.x * blockDim.x + threadIdx.x;
    if (idx >= NN * CH) return;
    int node = idx >> 7;
    int c    = idx & 127;
    float d = g_dinv[node];
    hout[idx] = hin[idx] * d * d + __ldg(&bias[c]);
}

// one warp per edge: gather h[col]*dinv[row]*dinv[col], scatter-add to out[row]
__global__ void k_agg_edge(const void* __restrict__ ei,
                           const float* __restrict__ hin,
                           float* __restrict__ hout) {
    int e = blockIdx.x * 8 + (threadIdx.x >> 5);
    if (e >= NE) return;
    int lane = threadIdx.x & 31;
    int r = edge_at(ei, e);
    int c = edge_at(ei, NE + e);
    float s = g_dinv[r] * g_dinv[c];
    float4 v = ((const float4*)(hin + (size_t)c * CH))[lane];
    float* dst = hout + (size_t)r * CH + lane * 4;
    atomicAdd(dst + 0, v.x * s);
    atomicAdd(dst + 1, v.y * s);
    atomicAdd(dst + 2, v.z * s);
    atomicAdd(dst + 3, v.w * s);
}

// ---------------- SGEMM: C[M x P] = (reluA? relu(A) : A)[M x 128] @ W[128 x P] (+bias) ----
// BM=64, BN=64, BK=64, 4x4 per-thread micro-tile, 256 threads.
__global__ __launch_bounds__(256) void k_sgemm128(
    const float* __restrict__ A, const float* __restrict__ W,
    const float* __restrict__ bias, float* __restrict__ C,
    int M, int P, int reluA)
{
    __shared__ float As[64][68];   // [row][k], pad 68 (mult of 4, conflict-free)
    __shared__ float Bs[64][64];   // [k][col]

    int tid = threadIdx.x;
    int rowBase = blockIdx.x * 64;
    int colBase = blockIdx.y * 64;
    int tx = tid & 15;             // 16 col-groups
    int ty = tid >> 4;             // 16 row-groups

    float acc[4][4] = {};

    bool fastW = ((P & 3) == 0) && (colBase + 64 <= P);

    for (int ko = 0; ko < 128; ko += 64) {
        // ---- load A tile (64x64 of the 128-wide row), vectorized ----
        #pragma unroll
        for (int it = 0; it < 4; ++it) {
            int idx = tid + it * 256;           // 0..1023 (float4 granules)
            int r  = idx >> 4;                  // 16 float4 per row
            int k4 = (idx & 15) << 2;
            float4 v = make_float4(0.f, 0.f, 0.f, 0.f);
            int gr = rowBase + r;
            if (gr < M)
                v = *(const float4*)(A + (size_t)gr * CH + ko + k4);
            if (reluA) {
                v.x = fmaxf(v.x, 0.f); v.y = fmaxf(v.y, 0.f);
                v.z = fmaxf(v.z, 0.f); v.w = fmaxf(v.w, 0.f);
            }
            *(float4*)&As[r][k4] = v;
        }
        // ---- load W tile ----
        if (fastW) {
            #pragma unroll
            for (int it = 0; it < 4; ++it) {
                int idx = tid + it * 256;
                int k  = idx >> 4;
                int c4 = (idx & 15) << 2;
                float4 v = *(const float4*)(W + (size_t)(ko + k) * P + colBase + c4);
                *(float4*)&Bs[k][c4] = v;
            }
        } else {
            #pragma unroll
            for (int it = 0; it < 16; ++it) {
                int idx = tid + it * 256;
                int k = idx >> 6;
                int c = idx & 63;
                float v = 0.f;
                if (colBase + c < P)
                    v = W[(size_t)(ko + k) * P + colBase + c];
                Bs[k][c] = v;
            }
        }
        __syncthreads();

        // ---- compute ----
        #pragma unroll 8
        for (int k = 0; k < 64; ++k) {
            float a0 = As[ty * 4 + 0][k];
            float a1 = As[ty * 4 + 1][k];
            float a2 = As[ty * 4 + 2][k];
            float a3 = As[ty * 4 + 3][k];
            float4 w = *(const float4*)&Bs[k][tx * 4];
            acc[0][0] += a0 * w.x; acc[0][1] += a0 * w.y;
            acc[0][2] += a0 * w.z; acc[0][3] += a0 * w.w;
            acc[1][0] += a1 * w.x; acc[1][1] += a1 * w.y;
            acc[1][2] += a1 * w.z; acc[1][3] += a1 * w.w;
            acc[2][0] += a2 * w.x; acc[2][1] += a2 * w.y;
            acc[2][2] += a2 * w.z; acc[2][3] += a2 * w.w;
            acc[3][0] += a3 * w.x; acc[3][1] += a3 * w.y;
            acc[3][2] += a3 * w.z; acc[3][3] += a3 * w.w;
        }
        __syncthreads();
    }

    // ---- store ----
    #pragma unroll
    for (int i = 0; i < 4; ++i) {
        int gr = rowBase + ty * 4 + i;
        if (gr >= M) continue;
        #pragma unroll
        for (int j = 0; j < 4; ++j) {
            int gc = colBase + tx * 4 + j;
            if (gc < P) {
                float bv = bias ? __ldg(&bias[gc]) : 0.f;
                C[(size_t)gr * P + gc] = acc[i][j] + bv;
            }
        }
    }
}

// ---------------- launch ----------------
extern "C" void kernel_launch(void* const* d_in, const int* in_sizes, int n_in,
                              void* d_out, int out_size) {
    const float* x  = (const float*)d_in[0];
    const void*  ei = d_in[1];
    const float* W1 = (const float*)d_in[2];
    const float* b1 = (const float*)d_in[3];
    const float* W2 = (const float*)d_in[4];
    const float* b2 = (const float*)d_in[5];
    const float* Wt = (const float*)d_in[6];
    const float* bt = (const float*)d_in[7];
    const float* Ws = (const float*)d_in[8];
    const float* bs = (const float*)d_in[9];
    const float* Wf = (const float*)d_in[10];
    const float* bf = (const float*)d_in[11];
    const float* Wa = (const float*)d_in[12];
    const float* ba = (const float*)d_in[13];
    float* out = (float*)d_out;

    float *bufA, *bufB;
    cudaGetSymbolAddress((void**)&bufA, g_bufA);
    cudaGetSymbolAddress((void**)&bufB, g_bufB);

    const int T = 256;

    // dtype sniff + degree/normalization
    k_detect<<<1, 1>>>((const int*)ei);
    k_deg_init<<<(NN + T - 1) / T, T>>>();
    k_deg_edge<<<(NE + T - 1) / T, T>>>(ei);
    k_dinv<<<(NN + T - 1) / T, T>>>();

    dim3 blk(256);
    dim3 gHid((NN + 63) / 64, 2);   // P = 128 -> 2 column tiles

    // layer 1: h = x @ W1 ; agg = D^-1/2 (A+I) D^-1/2 h + b1
    k_sgemm128<<<gHid, blk>>>(x, W1, nullptr, bufA, NN, CH, 0);
    k_self_bias<<<(NN * CH + T - 1) / T, T>>>(bufA, bufB, b1);
    k_agg_edge<<<(NE + 7) / 8, T>>>(ei, bufA, bufB);

    // layer 2: relu fused into A-load; emb = agg(h2) + b2
    k_sgemm128<<<gHid, blk>>>(bufB, W2, nullptr, bufA, NN, CH, 1);
    k_self_bias<<<(NN * CH + T - 1) / T, T>>>(bufA, bufB, b2);
    k_agg_edge<<<(NE + 7) / 8, T>>>(ei, bufA, bufB);

    // heads (output layout: concatenated tuple, row-major per head)
    k_sgemm128<<<dim3((NN + 63) / 64, 1), blk>>>(bufB, Wt, bt, out,                      NN,   30, 0);
    k_sgemm128<<<dim3((NN + 63) / 64, 1), blk>>>(bufB, Ws, bs, out + (size_t)NN * 30,    NN,   20, 0);
    k_sgemm128<<<dim3((NN + 63) / 64, 1), blk>>>(bufB, Wf, bf, out + (size_t)NN * 50,    NN,   15, 0);
    k_sgemm128<<<dim3((NN + 63) / 64, 32), blk>>>(bufB, Wa, ba, out + (size_t)NN * 65,   NN, 2000, 0);
}

// round 11
// speedup vs baseline: 1.6097x; 1.6097x over previous
#include <cuda_runtime.h>
#include <cuda_bf16.h>
#include <cstdint>

#define NN 50000
#define NE 800000
#define CH 128
#define NPAD 50048            // 391 * 128
#define MTILES 391

// ---------------- scratch (no allocations allowed) ----------------
__device__ float g_deg[NN];
__device__ float g_dinv[NN];
__device__ float g_bufA[(size_t)NN * CH];
__device__ float g_bufB[(size_t)NN * CH];
__device__ __nv_bfloat16 g_Xhi[(size_t)NPAD * CH];
__device__ __nv_bfloat16 g_Xlo[(size_t)NPAD * CH];
__device__ __nv_bfloat16 g_Whi[(size_t)2048 * CH];
__device__ __nv_bfloat16 g_Wlo[(size_t)2048 * CH];
__device__ float g_hbias[65];
__device__ int   g_is64;

// ================= helpers =================
__device__ __forceinline__ uint32_t smem_u32(const void* p) {
    uint32_t a;
    asm("{ .reg .u64 t; cvta.to.shared.u64 t, %1; cvt.u32.u64 %0, t; }" : "=r"(a) : "l"(p));
    return a;
}
__device__ __forceinline__ void ldmat_x4(uint32_t* r, uint32_t addr) {
    asm volatile("ldmatrix.sync.aligned.m8n8.x4.shared.b16 {%0,%1,%2,%3}, [%4];"
        : "=r"(r[0]), "=r"(r[1]), "=r"(r[2]), "=r"(r[3]) : "r"(addr));
}
__device__ __forceinline__ void mma16816(float* d, const uint32_t* a, const uint32_t* b) {
    asm volatile("mma.sync.aligned.m16n8k16.row.col.f32.bf16.bf16.f32 "
        "{%0,%1,%2,%3}, {%4,%5,%6,%7}, {%8,%9}, {%0,%1,%2,%3};"
        : "+f"(d[0]), "+f"(d[1]), "+f"(d[2]), "+f"(d[3])
        : "r"(a[0]), "r"(a[1]), "r"(a[2]), "r"(a[3]), "r"(b[0]), "r"(b[1]));
}

// ---------------- edge-index dtype sniff ----------------
__global__ void k_detect(const int* __restrict__ ei32) {
    int z = 0;
    for (int i = 1; i < 256; i += 2)
        if (ei32[i] == 0) z++;
    g_is64 = (z > 64) ? 1 : 0;
}
__device__ __forceinline__ int edge_at(const void* __restrict__ ei, int pos) {
    if (g_is64) return (int)((const long long*)ei)[pos];
    return ((const int*)ei)[pos];
}

// ---------------- degree / normalization ----------------
__global__ void k_deg_init() {
    int i = blockIdx.x * blockDim.x + threadIdx.x;
    if (i < NN) g_deg[i] = 1.0f;
}
__global__ void k_deg_edge(const void* __restrict__ ei) {
    int e = blockIdx.x * blockDim.x + threadIdx.x;
    if (e < NE) atomicAdd(&g_deg[edge_at(ei, e)], 1.0f);
}
__global__ void k_dinv() {
    int i = blockIdx.x * blockDim.x + threadIdx.x;
    if (i < NN) g_dinv[i] = rsqrtf(g_deg[i]);
}

// ---------------- aggregation ----------------
__global__ void k_self_bias(const float* __restrict__ hin, float* __restrict__ hout,
                            const float* __restrict__ bias) {
    int idx = blockIdx.x * blockDim.x + threadIdx.x;
    if (idx >= NN * CH) return;
    int node = idx >> 7;
    int c = idx & 127;
    float d = g_dinv[node];
    hout[idx] = hin[idx] * d * d + __ldg(&bias[c]);
}

__global__ void k_agg_edge(const void* __restrict__ ei, const float* __restrict__ hin,
                           float* __restrict__ hout) {
    int e = blockIdx.x * 8 + (threadIdx.x >> 5);
    if (e >= NE) return;
    int lane = threadIdx.x & 31;
    int r = edge_at(ei, e);
    int c = edge_at(ei, NE + e);
    float s = g_dinv[r] * g_dinv[c];
    float4 v = ((const float4*)(hin + (size_t)c * CH))[lane];
    float* dst = hout + (size_t)r * CH + lane * 4;
    atomicAdd(dst + 0, v.x * s);
    atomicAdd(dst + 1, v.y * s);
    atomicAdd(dst + 2, v.z * s);
    atomicAdd(dst + 3, v.w * s);
}

// ---------------- fp32 -> bf16 hi/lo split conversions ----------------
__global__ void k_conv_feat(const float* __restrict__ src, int rows, int relu) {
    int i4 = blockIdx.x * blockDim.x + threadIdx.x;          // float4 granules
    if (i4 >= NPAD * CH / 4) return;
    int row = i4 >> 5;
    float4 v = make_float4(0.f, 0.f, 0.f, 0.f);
    if (row < rows) v = ((const float4*)src)[i4];
    if (relu) {
        v.x = fmaxf(v.x, 0.f); v.y = fmaxf(v.y, 0.f);
        v.z = fmaxf(v.z, 0.f); v.w = fmaxf(v.w, 0.f);
    }
    __nv_bfloat16 h0 = __float2bfloat16(v.x), h1 = __float2bfloat16(v.y);
    __nv_bfloat16 h2 = __float2bfloat16(v.z), h3 = __float2bfloat16(v.w);
    __nv_bfloat162 hA = __nv_bfloat162(h0, h1), hB = __nv_bfloat162(h2, h3);
    __nv_bfloat162 lA = __nv_bfloat162(__float2bfloat16(v.x - __bfloat162float(h0)),
                                       __float2bfloat16(v.y - __bfloat162float(h1)));
    __nv_bfloat162 lB = __nv_bfloat162(__float2bfloat16(v.z - __bfloat162float(h2)),
                                       __float2bfloat16(v.w - __bfloat162float(h3)));
    ((__nv_bfloat162*)g_Xhi)[i4 * 2] = hA;
    ((__nv_bfloat162*)g_Xhi)[i4 * 2 + 1] = hB;
    ((__nv_bfloat162*)g_Xlo)[i4 * 2] = lA;
    ((__nv_bfloat162*)g_Xlo)[i4 * 2 + 1] = lB;
}

// W [128 x P] row-major -> transposed padded [Ppad x 128] hi/lo (K-major rows)
__global__ void k_conv_w(const float* __restrict__ W, int P, int Ppad) {
    int idx = blockIdx.x * blockDim.x + threadIdx.x;
    if (idx >= Ppad * CH) return;
    int n = idx >> 7, k = idx & 127;
    float v = (n < P) ? W[(size_t)k * P + n] : 0.f;
    __nv_bfloat16 h = __float2bfloat16(v);
    g_Whi[idx] = h;
    g_Wlo[idx] = __float2bfloat16(v - __bfloat162float(h));
}

// combined small-head weights: rows 0..29 Wt, 30..49 Ws, 50..64 Wf, rest 0
__global__ void k_conv_heads(const float* __restrict__ Wt, const float* __restrict__ Ws,
                             const float* __restrict__ Wf) {
    int idx = blockIdx.x * blockDim.x + threadIdx.x;
    if (idx >= 128 * CH) return;
    int n = idx >> 7, k = idx & 127;
    float v = 0.f;
    if (n < 30)      v = Wt[(size_t)k * 30 + n];
    else if (n < 50) v = Ws[(size_t)k * 20 + (n - 30)];
    else if (n < 65) v = Wf[(size_t)k * 15 + (n - 50)];
    __nv_bfloat16 h = __float2bfloat16(v);
    g_Whi[idx] = h;
    g_Wlo[idx] = __float2bfloat16(v - __bfloat162float(h));
}
__global__ void k_pack_bias(const float* __restrict__ bt, const float* __restrict__ bs,
                            const float* __restrict__ bf) {
    int i = threadIdx.x;
    if (i < 30)      g_hbias[i] = bt[i];
    else if (i < 50) g_hbias[i] = bs[i - 30];
    else if (i < 65) g_hbias[i] = bf[i - 50];
}

// ---------------- mma.sync bf16-split GEMM ----------------
// C[M x P] = A[M x 128] @ W[128 x P] (+bias), A/W pre-split into bf16 hi/lo.
// BM=128, BN=64, K=128 fully staged. 256 threads = 8 warps, warp tile 32x32.
// smem tiles: row-major [rows][16 chunks of 16B], phys chunk = c ^ (r&7).
#define SM_AH 0
#define SM_AL 32768
#define SM_BH 65536
#define SM_BL (65536 + 16384)
#define SM_TOTAL (65536 + 32768)

__device__ __forceinline__ uint32_t tile_off(int row, int chunk) {
    return (uint32_t)row * 256u + (uint32_t)((chunk ^ (row & 7)) << 4);
}

__global__ __launch_bounds__(256, 2) void k_mma_gemm(
    const __nv_bfloat16* __restrict__ Ah, const __nv_bfloat16* __restrict__ Al,
    const __nv_bfloat16* __restrict__ Bh, const __nv_bfloat16* __restrict__ Bl,
    const float* __restrict__ bias, float* __restrict__ C,
    int M, int P, int ntPerY, int mode,
    float* __restrict__ o1, float* __restrict__ o2, float* __restrict__ o3)
{
    extern __shared__ __align__(1024) char smem[];
    uint32_t sb = smem_u32(smem);
    int tid = threadIdx.x;
    int lane = tid & 31;
    int wid = tid >> 5;
    int wm = wid & 3;            // 4 warps along M (32 rows each)
    int wn = wid >> 2;           // 2 warps along N (32 cols each)
    int g = lane >> 3, i8 = lane & 7;
    int mBase = blockIdx.x * 128;
    int ntBegin = blockIdx.y * ntPerY;

    // ---- stage A tiles (hi, lo): 128 rows x 256B ----
    #pragma unroll
    for (int it = 0; it < 8; ++it) {
        int id = tid + it * 256;             // 0..2047
        int r = id >> 4;
        int c = id & 15;
        uint32_t so = tile_off(r, c);
        *(uint4*)(smem + SM_AH + so) = ((const uint4*)(Ah + (size_t)(mBase + r) * CH))[c];
        *(uint4*)(smem + SM_AL + so) = ((const uint4*)(Al + (size_t)(mBase + r) * CH))[c];
    }

    for (int t = 0; t < ntPerY; ++t) {
        int nt = ntBegin + t;
        int colBase = nt * 64;
        __syncthreads();   // previous iter's ldmatrix done before overwrite
        // ---- stage B tiles: 64 rows x 256B ----
        #pragma unroll
        for (int it = 0; it < 4; ++it) {
            int id = tid + it * 256;         // 0..1023
            int r = id >> 4;
            int c = id & 15;
            uint32_t so = tile_off(r, c);
            *(uint4*)(smem + SM_BH + so) = ((const uint4*)(Bh + (size_t)(colBase + r) * CH))[c];
            *(uint4*)(smem + SM_BL + so) = ((const uint4*)(Bl + (size_t)(colBase + r) * CH))[c];
        }
        __syncthreads();

        float acc[2][4][4];
        #pragma unroll
        for (int a = 0; a < 2; ++a)
            #pragma unroll
            for (int b = 0; b < 4; ++b)
                #pragma unroll
                for (int c = 0; c < 4; ++c) acc[a][b][c] = 0.f;

        #pragma unroll
        for (int ks = 0; ks < 8; ++ks) {
            int c0 = ks * 2;
            uint32_t a_h[2][4], a_l[2][4], b_h[2][4], b_l[2][4];
            #pragma unroll
            for (int mb = 0; mb < 2; ++mb) {
                int row = wm * 32 + mb * 16 + (g & 1) * 8 + i8;
                int ch = c0 + (g >> 1);
                uint32_t off = tile_off(row, ch);
                ldmat_x4(a_h[mb], sb + SM_AH + off);
                ldmat_x4(a_l[mb], sb + SM_AL + off);
            }
            #pragma unroll
            for (int np = 0; np < 2; ++np) {
                int rn = wn * 32 + np * 16 + (g >> 1) * 8 + i8;
                int ch = c0 + (g & 1);
                uint32_t off = tile_off(rn, ch);
                ldmat_x4(b_h[np], sb + SM_BH + off);
                ldmat_x4(b_l[np], sb + SM_BL + off);
            }
            #pragma unroll
            for (int mb = 0; mb < 2; ++mb)
                #pragma unroll
                for (int nb = 0; nb < 4; ++nb) {
                    float* ac = acc[mb][nb];
                    const uint32_t* bh = &b_h[nb >> 1][(nb & 1) * 2];
                    const uint32_t* bl = &b_l[nb >> 1][(nb & 1) * 2];
                    mma16816(ac, a_h[mb], bh);   // Ah*Bh
                    mma16816(ac, a_h[mb], bl);   // Ah*Bl
                    mma16816(ac, a_l[mb], bh);   // Al*Bh
                }
        }

        // ---- epilogue ----
        #pragma unroll
        for (int mb = 0; mb < 2; ++mb) {
            int gr = mBase + wm * 32 + mb * 16 + (lane >> 2);
            #pragma unroll
            for (int nb = 0; nb < 4; ++nb) {
                int gc = colBase + wn * 32 + nb * 8 + (lane & 3) * 2;
                float* ac = acc[mb][nb];
                if (mode == 0) {
                    if (gc < P) {
                        float bx = bias ? __ldg(bias + gc) : 0.f;
                        float by = bias ? __ldg(bias + gc + 1) : 0.f;
                        if (gr < M)
                            *(float2*)(C + (size_t)gr * P + gc) =
                                make_float2(ac[0] + bx, ac[1] + by);
                        if (gr + 8 < M)
                            *(float2*)(C + (size_t)(gr + 8) * P + gc) =
                                make_float2(ac[2] + bx, ac[3] + by);
                    }
                } else {
                    #pragma unroll
                    for (int e = 0; e < 4; ++e) {
                        int c = gc + (e & 1);
                        int r = gr + (e >> 1) * 8;
                        if (c < 65 && r < M) {
                            float v = ac[e] + g_hbias[c];
                            if (c < 30)      o1[(size_t)r * 30 + c] = v;
                            else if (c < 50) o2[(size_t)r * 20 + (c - 30)] = v;
                            else             o3[(size_t)r * 15 + (c - 50)] = v;
                        }
                    }
                }
            }
        }
    }
}

// ---------------- launch ----------------
extern "C" void kernel_launch(void* const* d_in, const int* in_sizes, int n_in,
                              void* d_out, int out_size) {
    const float* x  = (const float*)d_in[0];
    const void*  ei = d_in[1];
    const float* W1 = (const float*)d_in[2];
    const float* b1 = (const float*)d_in[3];
    const float* W2 = (const float*)d_in[4];
    const float* b2 = (const float*)d_in[5];
    const float* Wt = (const float*)d_in[6];
    const float* bt = (const float*)d_in[7];
    const float* Ws = (const float*)d_in[8];
    const float* bs = (const float*)d_in[9];
    const float* Wf = (const float*)d_in[10];
    const float* bf = (const float*)d_in[11];
    const float* Wa = (const float*)d_in[12];
    const float* ba = (const float*)d_in[13];
    float* out = (float*)d_out;

    float *bufA, *bufB;
    __nv_bfloat16 *Xhi, *Xlo, *Whi, *Wlo;
    cudaGetSymbolAddress((void**)&bufA, g_bufA);
    cudaGetSymbolAddress((void**)&bufB, g_bufB);
    cudaGetSymbolAddress((void**)&Xhi, g_Xhi);
    cudaGetSymbolAddress((void**)&Xlo, g_Xlo);
    cudaGetSymbolAddress((void**)&Whi, g_Whi);
    cudaGetSymbolAddress((void**)&Wlo, g_Wlo);

    cudaFuncSetAttribute(k_mma_gemm, cudaFuncAttributeMaxDynamicSharedMemorySize, SM_TOTAL);

    const int T = 256;
    const int featBlocks = (NPAD * CH / 4 + T - 1) / T;

    k_detect<<<1, 1>>>((const int*)ei);
    k_deg_init<<<(NN + T - 1) / T, T>>>();
    k_deg_edge<<<(NE + T - 1) / T, T>>>(ei);
    k_dinv<<<(NN + T - 1) / T, T>>>();

    // ---- layer 1 ----
    k_conv_feat<<<featBlocks, T>>>(x, NN, 0);
    k_conv_w<<<(128 * CH + T - 1) / T, T>>>(W1, CH, 128);
    k_mma_gemm<<<dim3(MTILES, 2), 256, SM_TOTAL>>>(Xhi, Xlo, Whi, Wlo, nullptr, bufA,
                                                   NN, CH, 1, 0, nullptr, nullptr, nullptr);
    k_self_bias<<<(NN * CH + T - 1) / T, T>>>(bufA, bufB, b1);
    k_agg_edge<<<(NE + 7) / 8, T>>>(ei, bufA, bufB);

    // ---- layer 2 (relu fused into conversion) ----
    k_conv_feat<<<featBlocks, T>>>(bufB, NN, 1);
    k_conv_w<<<(128 * CH + T - 1) / T, T>>>(W2, CH, 128);
    k_mma_gemm<<<dim3(MTILES, 2), 256, SM_TOTAL>>>(Xhi, Xlo, Whi, Wlo, nullptr, bufA,
                                                   NN, CH, 1, 0, nullptr, nullptr, nullptr);
    k_self_bias<<<(NN * CH + T - 1) / T, T>>>(bufA, bufB, b2);
    k_agg_edge<<<(NE + 7) / 8, T>>>(ei, bufA, bufB);

    // ---- heads ----
    k_conv_feat<<<featBlocks, T>>>(bufB, NN, 0);

    // small heads combined (type 30 | school 20 | time 15), cols 0..64 of 128
    k_conv_heads<<<(128 * CH + T - 1) / T, T>>>(Wt, Ws, Wf);
    k_pack_bias<<<1, 65>>>(bt, bs, bf);
    k_mma_gemm<<<dim3(MTILES, 2), 256, SM_TOTAL>>>(Xhi, Xlo, Whi, Wlo, nullptr, nullptr,
                                                   NN, 65, 1, 1,
                                                   out, out + (size_t)NN * 30,
                                                   out + (size_t)NN * 50);

    // author head P=2000 (padded 2048 -> 32 n-tiles of 64, split 4 ways)
    k_conv_w<<<(2048 * CH + T - 1) / T, T>>>(Wa, 2000, 2048);
    k_mma_gemm<<<dim3(MTILES, 4), 256, SM_TOTAL>>>(Xhi, Xlo, Whi, Wlo, ba,
                                                   out + (size_t)NN * 65,
                                                   NN, 2000, 8, 0, nullptr, nullptr, nullptr);
}

// round 12
// speedup vs baseline: 1.9376x; 1.2037x over previous
#include <cuda_runtime.h>
#include <cuda_bf16.h>
#include <cstdint>

#define NN 50000
#define NE 800000
#define CH 128
#define NPAD 50048            // 391 * 128
#define MTILES 391

// ---------------- scratch (no allocations allowed) ----------------
__device__ float g_dinv[NN];
__device__ int   g_cnt[NN];
__device__ int   g_rowstart[NN + 1];
__device__ int   g_cursor[NN];
__device__ int   g_ecol[NE];
__device__ float g_enorm[NE];
__device__ float g_bufA[(size_t)NN * CH];
__device__ __nv_bfloat16 g_Xhi[(size_t)NPAD * CH];
__device__ __nv_bfloat16 g_Xlo[(size_t)NPAD * CH];
__device__ __nv_bfloat16 g_Whi[(size_t)2048 * CH];
__device__ __nv_bfloat16 g_Wlo[(size_t)2048 * CH];
__device__ float g_hbias[65];
__device__ int   g_is64;

// ================= helpers =================
__device__ __forceinline__ uint32_t smem_u32(const void* p) {
    uint32_t a;
    asm("{ .reg .u64 t; cvta.to.shared.u64 t, %1; cvt.u32.u64 %0, t; }" : "=r"(a) : "l"(p));
    return a;
}
__device__ __forceinline__ void ldmat_x4(uint32_t* r, uint32_t addr) {
    asm volatile("ldmatrix.sync.aligned.m8n8.x4.shared.b16 {%0,%1,%2,%3}, [%4];"
        : "=r"(r[0]), "=r"(r[1]), "=r"(r[2]), "=r"(r[3]) : "r"(addr));
}
__device__ __forceinline__ void mma16816(float* d, const uint32_t* a, const uint32_t* b) {
    asm volatile("mma.sync.aligned.m16n8k16.row.col.f32.bf16.bf16.f32 "
        "{%0,%1,%2,%3}, {%4,%5,%6,%7}, {%8,%9}, {%0,%1,%2,%3};"
        : "+f"(d[0]), "+f"(d[1]), "+f"(d[2]), "+f"(d[3])
        : "r"(a[0]), "r"(a[1]), "r"(a[2]), "r"(a[3]), "r"(b[0]), "r"(b[1]));
}

// ---------------- edge-index dtype sniff ----------------
__global__ void k_detect(const int* __restrict__ ei32) {
    int z = 0;
    for (int i = 1; i < 256; i += 2)
        if (ei32[i] == 0) z++;
    g_is64 = (z > 64) ? 1 : 0;
}
__device__ __forceinline__ int edge_at(const void* __restrict__ ei, int pos) {
    if (g_is64) return (int)((const long long*)ei)[pos];
    return ((const int*)ei)[pos];
}

// ---------------- CSR build ----------------
__global__ void k_zero() {
    int i = blockIdx.x * blockDim.x + threadIdx.x;
    if (i < NN) g_cnt[i] = 0;
    if (i < (NPAD - NN) * CH) {           // zero pad rows of GEMM input
        g_Xhi[(size_t)NN * CH + i] = __float2bfloat16(0.f);
        g_Xlo[(size_t)NN * CH + i] = __float2bfloat16(0.f);
    }
}
__global__ void k_cnt(const void* __restrict__ ei) {
    int e = blockIdx.x * blockDim.x + threadIdx.x;
    if (e < NE) atomicAdd(&g_cnt[edge_at(ei, e)], 1);
}
__global__ void k_dinv() {
    int i = blockIdx.x * blockDim.x + threadIdx.x;
    if (i < NN) g_dinv[i] = rsqrtf((float)(g_cnt[i] + 1));
}

// single-block exclusive scan of g_cnt -> g_rowstart / g_cursor
__global__ void k_scan() {
    __shared__ int swarp[32];
    __shared__ int s_carry;
    int tid = threadIdx.x, lane = tid & 31, wid = tid >> 5;
    if (tid == 0) s_carry = 0;
    __syncthreads();
    for (int base = 0; base < NN; base += 1024) {
        int i = base + tid;
        int v = (i < NN) ? g_cnt[i] : 0;
        int incl = v;
        #pragma unroll
        for (int d = 1; d < 32; d <<= 1) {
            int n = __shfl_up_sync(0xffffffffu, incl, d);
            if (lane >= d) incl += n;
        }
        if (lane == 31) swarp[wid] = incl;
        __syncthreads();
        if (wid == 0) {
            int wv = swarp[lane];
            int wincl = wv;
            #pragma unroll
            for (int d = 1; d < 32; d <<= 1) {
                int n = __shfl_up_sync(0xffffffffu, wincl, d);
                if (lane >= d) wincl += n;
            }
            swarp[lane] = wincl - wv;   // exclusive warp offset
        }
        __syncthreads();
        int excl = s_carry + swarp[wid] + incl - v;
        if (i < NN) { g_rowstart[i] = excl; g_cursor[i] = excl; }
        __syncthreads();
        if (tid == 1023) s_carry = excl + v;
        __syncthreads();
    }
    if (threadIdx.x == 0) g_rowstart[NN] = s_carry;
}

__global__ void k_fill(const void* __restrict__ ei) {
    int e = blockIdx.x * blockDim.x + threadIdx.x;
    if (e >= NE) return;
    int r = edge_at(ei, e);
    int c = edge_at(ei, NE + e);
    int pos = atomicAdd(&g_cursor[r], 1);
    g_ecol[pos] = c;
    g_enorm[pos] = g_dinv[r] * g_dinv[c];
}

// ---------------- CSR gather aggregation (fused: self + bias + relu + bf16 split) ----
// one warp per node; writes bf16 hi/lo GEMM inputs directly.
__global__ __launch_bounds__(256) void k_agg_csr(const float* __restrict__ hin,
                                                 const float* __restrict__ bias, int relu) {
    int node = blockIdx.x * 8 + (threadIdx.x >> 5);
    if (node >= NN) return;
    int lane = threadIdx.x & 31;
    float d = g_dinv[node];
    float dd = d * d;
    float4 acc = ((const float4*)(hin + (size_t)node * CH))[lane];
    acc.x *= dd; acc.y *= dd; acc.z *= dd; acc.w *= dd;

    int s = g_rowstart[node], e = g_rowstart[node + 1];
    int j = s;
    for (; j + 2 <= e; j += 2) {
        int   c0 = g_ecol[j],     c1 = g_ecol[j + 1];
        float w0 = g_enorm[j],    w1 = g_enorm[j + 1];
        float4 v0 = ((const float4*)(hin + (size_t)c0 * CH))[lane];
        float4 v1 = ((const float4*)(hin + (size_t)c1 * CH))[lane];
        acc.x += v0.x * w0 + v1.x * w1;
        acc.y += v0.y * w0 + v1.y * w1;
        acc.z += v0.z * w0 + v1.z * w1;
        acc.w += v0.w * w0 + v1.w * w1;
    }
    if (j < e) {
        int c0 = g_ecol[j];
        float w0 = g_enorm[j];
        float4 v0 = ((const float4*)(hin + (size_t)c0 * CH))[lane];
        acc.x += v0.x * w0; acc.y += v0.y * w0;
        acc.z += v0.z * w0; acc.w += v0.w * w0;
    }

    float4 b = ((const float4*)bias)[lane];
    acc.x += b.x; acc.y += b.y; acc.z += b.z; acc.w += b.w;
    if (relu) {
        acc.x = fmaxf(acc.x, 0.f); acc.y = fmaxf(acc.y, 0.f);
        acc.z = fmaxf(acc.z, 0.f); acc.w = fmaxf(acc.w, 0.f);
    }
    // bf16 hi/lo split
    __nv_bfloat16 h0 = __float2bfloat16(acc.x), h1 = __float2bfloat16(acc.y);
    __nv_bfloat16 h2 = __float2bfloat16(acc.z), h3 = __float2bfloat16(acc.w);
    __nv_bfloat162 hA(h0, h1), hB(h2, h3);
    __nv_bfloat162 lA(__float2bfloat16(acc.x - __bfloat162float(h0)),
                      __float2bfloat16(acc.y - __bfloat162float(h1)));
    __nv_bfloat162 lB(__float2bfloat16(acc.z - __bfloat162float(h2)),
                      __float2bfloat16(acc.w - __bfloat162float(h3)));
    size_t o = (size_t)node * 64 + lane * 2;
    ((__nv_bfloat162*)g_Xhi)[o]     = hA;
    ((__nv_bfloat162*)g_Xhi)[o + 1] = hB;
    ((__nv_bfloat162*)g_Xlo)[o]     = lA;
    ((__nv_bfloat162*)g_Xlo)[o + 1] = lB;
}

// ---------------- fp32 -> bf16 hi/lo split (layer-1 input x only) ----------------
__global__ void k_conv_feat(const float* __restrict__ src, int rows) {
    int i4 = blockIdx.x * blockDim.x + threadIdx.x;
    if (i4 >= NPAD * CH / 4) return;
    int row = i4 >> 5;
    float4 v = make_float4(0.f, 0.f, 0.f, 0.f);
    if (row < rows) v = ((const float4*)src)[i4];
    __nv_bfloat16 h0 = __float2bfloat16(v.x), h1 = __float2bfloat16(v.y);
    __nv_bfloat16 h2 = __float2bfloat16(v.z), h3 = __float2bfloat16(v.w);
    __nv_bfloat162 hA(h0, h1), hB(h2, h3);
    __nv_bfloat162 lA(__float2bfloat16(v.x - __bfloat162float(h0)),
                      __float2bfloat16(v.y - __bfloat162float(h1)));
    __nv_bfloat162 lB(__float2bfloat16(v.z - __bfloat162float(h2)),
                      __float2bfloat16(v.w - __bfloat162float(h3)));
    ((__nv_bfloat162*)g_Xhi)[i4 * 2] = hA;
    ((__nv_bfloat162*)g_Xhi)[i4 * 2 + 1] = hB;
    ((__nv_bfloat162*)g_Xlo)[i4 * 2] = lA;
    ((__nv_bfloat162*)g_Xlo)[i4 * 2 + 1] = lB;
}

// W [128 x P] row-major -> transposed padded [Ppad x 128] hi/lo (K-major rows)
__global__ void k_conv_w(const float* __restrict__ W, int P, int Ppad) {
    int idx = blockIdx.x * blockDim.x + threadIdx.x;
    if (idx >= Ppad * CH) return;
    int n = idx >> 7, k = idx & 127;
    float v = (n < P) ? W[(size_t)k * P + n] : 0.f;
    __nv_bfloat16 h = __float2bfloat16(v);
    g_Whi[idx] = h;
    g_Wlo[idx] = __float2bfloat16(v - __bfloat162float(h));
}

// combined small-head weights: rows 0..29 Wt, 30..49 Ws, 50..64 Wf, rest 0
__global__ void k_conv_heads(const float* __restrict__ Wt, const float* __restrict__ Ws,
                             const float* __restrict__ Wf) {
    int idx = blockIdx.x * blockDim.x + threadIdx.x;
    if (idx >= 128 * CH) return;
    int n = idx >> 7, k = idx & 127;
    float v = 0.f;
    if (n < 30)      v = Wt[(size_t)k * 30 + n];
    else if (n < 50) v = Ws[(size_t)k * 20 + (n - 30)];
    else if (n < 65) v = Wf[(size_t)k * 15 + (n - 50)];
    __nv_bfloat16 h = __float2bfloat16(v);
    g_Whi[idx] = h;
    g_Wlo[idx] = __float2bfloat16(v - __bfloat162float(h));
}
__global__ void k_pack_bias(const float* __restrict__ bt, const float* __restrict__ bs,
                            const float* __restrict__ bf) {
    int i = threadIdx.x;
    if (i < 30)      g_hbias[i] = bt[i];
    else if (i < 50) g_hbias[i] = bs[i - 30];
    else if (i < 65) g_hbias[i] = bf[i - 50];
}

// ---------------- mma.sync bf16-split GEMM ----------------
// C[M x P] = A[M x 128] @ W[128 x P] (+bias), A/W pre-split into bf16 hi/lo.
// BM=128, BN=64, K=128 fully staged. 256 threads = 8 warps, warp tile 32x32.
#define SM_AH 0
#define SM_AL 32768
#define SM_BH 65536
#define SM_BL (65536 + 16384)
#define SM_TOTAL (65536 + 32768)

__device__ __forceinline__ uint32_t tile_off(int row, int chunk) {
    return (uint32_t)row * 256u + (uint32_t)((chunk ^ (row & 7)) << 4);
}

__global__ __launch_bounds__(256, 2) void k_mma_gemm(
    const __nv_bfloat16* __restrict__ Ah, const __nv_bfloat16* __restrict__ Al,
    const __nv_bfloat16* __restrict__ Bh, const __nv_bfloat16* __restrict__ Bl,
    const float* __restrict__ bias, float* __restrict__ C,
    int M, int P, int ntPerY, int mode,
    float* __restrict__ o1, float* __restrict__ o2, float* __restrict__ o3)
{
    extern __shared__ __align__(1024) char smem[];
    uint32_t sb = smem_u32(smem);
    int tid = threadIdx.x;
    int lane = tid & 31;
    int wid = tid >> 5;
    int wm = wid & 3;
    int wn = wid >> 2;
    int g = lane >> 3, i8 = lane & 7;
    int mBase = blockIdx.x * 128;
    int ntBegin = blockIdx.y * ntPerY;

    #pragma unroll
    for (int it = 0; it < 8; ++it) {
        int id = tid + it * 256;
        int r = id >> 4;
        int c = id & 15;
        uint32_t so = tile_off(r, c);
        *(uint4*)(smem + SM_AH + so) = ((const uint4*)(Ah + (size_t)(mBase + r) * CH))[c];
        *(uint4*)(smem + SM_AL + so) = ((const uint4*)(Al + (size_t)(mBase + r) * CH))[c];
    }

    for (int t = 0; t < ntPerY; ++t) {
        int nt = ntBegin + t;
        int colBase = nt * 64;
        __syncthreads();
        #pragma unroll
        for (int it = 0; it < 4; ++it) {
            int id = tid + it * 256;
            int r = id >> 4;
            int c = id & 15;
            uint32_t so = tile_off(r, c);
            *(uint4*)(smem + SM_BH + so) = ((const uint4*)(Bh + (size_t)(colBase + r) * CH))[c];
            *(uint4*)(smem + SM_BL + so) = ((const uint4*)(Bl + (size_t)(colBase + r) * CH))[c];
        }
        __syncthreads();

        float acc[2][4][4];
        #pragma unroll
        for (int a = 0; a < 2; ++a)
            #pragma unroll
            for (int b = 0; b < 4; ++b)
                #pragma unroll
                for (int c = 0; c < 4; ++c) acc[a][b][c] = 0.f;

        #pragma unroll
        for (int ks = 0; ks < 8; ++ks) {
            int c0 = ks * 2;
            uint32_t a_h[2][4], a_l[2][4], b_h[2][4], b_l[2][4];
            #pragma unroll
            for (int mb = 0; mb < 2; ++mb) {
                int row = wm * 32 + mb * 16 + (g & 1) * 8 + i8;
                int ch = c0 + (g >> 1);
                uint32_t off = tile_off(row, ch);
                ldmat_x4(a_h[mb], sb + SM_AH + off);
                ldmat_x4(a_l[mb], sb + SM_AL + off);
            }
            #pragma unroll
            for (int np = 0; np < 2; ++np) {
                int rn = wn * 32 + np * 16 + (g >> 1) * 8 + i8;
                int ch = c0 + (g & 1);
                uint32_t off = tile_off(rn, ch);
                ldmat_x4(b_h[np], sb + SM_BH + off);
                ldmat_x4(b_l[np], sb + SM_BL + off);
            }
            #pragma unroll
            for (int mb = 0; mb < 2; ++mb)
                #pragma unroll
                for (int nb = 0; nb < 4; ++nb) {
                    float* ac = acc[mb][nb];
                    const uint32_t* bh = &b_h[nb >> 1][(nb & 1) * 2];
                    const uint32_t* bl = &b_l[nb >> 1][(nb & 1) * 2];
                    mma16816(ac, a_h[mb], bh);
                    mma16816(ac, a_h[mb], bl);
                    mma16816(ac, a_l[mb], bh);
                }
        }

        #pragma unroll
        for (int mb = 0; mb < 2; ++mb) {
            int gr = mBase + wm * 32 + mb * 16 + (lane >> 2);
            #pragma unroll
            for (int nb = 0; nb < 4; ++nb) {
                int gc = colBase + wn * 32 + nb * 8 + (lane & 3) * 2;
                float* ac = acc[mb][nb];
                if (mode == 0) {
                    if (gc < P) {
                        float bx = bias ? __ldg(bias + gc) : 0.f;
                        float by = bias ? __ldg(bias + gc + 1) : 0.f;
                        if (gr < M)
                            *(float2*)(C + (size_t)gr * P + gc) =
                                make_float2(ac[0] + bx, ac[1] + by);
                        if (gr + 8 < M)
                            *(float2*)(C + (size_t)(gr + 8) * P + gc) =
                                make_float2(ac[2] + bx, ac[3] + by);
                    }
                } else {
                    #pragma unroll
                    for (int e = 0; e < 4; ++e) {
                        int c = gc + (e & 1);
                        int r = gr + (e >> 1) * 8;
                        if (c < 65 && r < M) {
                            float v = ac[e] + g_hbias[c];
                            if (c < 30)      o1[(size_t)r * 30 + c] = v;
                            else if (c < 50) o2[(size_t)r * 20 + (c - 30)] = v;
                            else             o3[(size_t)r * 15 + (c - 50)] = v;
                        }
                    }
                }
            }
        }
    }
}

// ---------------- launch ----------------
extern "C" void kernel_launch(void* const* d_in, const int* in_sizes, int n_in,
                              void* d_out, int out_size) {
    const float* x  = (const float*)d_in[0];
    const void*  ei = d_in[1];
    const float* W1 = (const float*)d_in[2];
    const float* b1 = (const float*)d_in[3];
    const float* W2 = (const float*)d_in[4];
    const float* b2 = (const float*)d_in[5];
    const float* Wt = (const float*)d_in[6];
    const float* bt = (const float*)d_in[7];
    const float* Ws = (const float*)d_in[8];
    const float* bs = (const float*)d_in[9];
    const float* Wf = (const float*)d_in[10];
    const float* bf = (const float*)d_in[11];
    const float* Wa = (const float*)d_in[12];
    const float* ba = (const float*)d_in[13];
    float* out = (float*)d_out;

    float *bufA;
    __nv_bfloat16 *Xhi, *Xlo, *Whi, *Wlo;
    cudaGetSymbolAddress((void**)&bufA, g_bufA);
    cudaGetSymbolAddress((void**)&Xhi, g_Xhi);
    cudaGetSymbolAddress((void**)&Xlo, g_Xlo);
    cudaGetSymbolAddress((void**)&Whi, g_Whi);
    cudaGetSymbolAddress((void**)&Wlo, g_Wlo);

    cudaFuncSetAttribute(k_mma_gemm, cudaFuncAttributeMaxDynamicSharedMemorySize, SM_TOTAL);

    const int T = 256;
    const int featBlocks = (NPAD * CH / 4 + T - 1) / T;

    // ---- CSR build ----
    k_detect<<<1, 1>>>((const int*)ei);
    k_zero<<<(NN + T - 1) / T, T>>>();
    k_cnt<<<(NE + T - 1) / T, T>>>(ei);
    k_dinv<<<(NN + T - 1) / T, T>>>();
    k_scan<<<1, 1024>>>();
    k_fill<<<(NE + T - 1) / T, T>>>(ei);

    // ---- layer 1 ----
    k_conv_feat<<<featBlocks, T>>>(x, NN);
    k_conv_w<<<(128 * CH + T - 1) / T, T>>>(W1, CH, 128);
    k_mma_gemm<<<dim3(MTILES, 2), 256, SM_TOTAL>>>(Xhi, Xlo, Whi, Wlo, nullptr, bufA,
                                                   NN, CH, 1, 0, nullptr, nullptr, nullptr);
    k_agg_csr<<<(NN + 7) / 8, 256>>>(bufA, b1, 1);   // + b1, relu, split -> Xhi/Xlo

    // ---- layer 2 ----
    k_conv_w<<<(128 * CH + T - 1) / T, T>>>(W2, CH, 128);
    k_mma_gemm<<<dim3(MTILES, 2), 256, SM_TOTAL>>>(Xhi, Xlo, Whi, Wlo, nullptr, bufA,
                                                   NN, CH, 1, 0, nullptr, nullptr, nullptr);
    k_agg_csr<<<(NN + 7) / 8, 256>>>(bufA, b2, 0);   // + b2, split -> Xhi/Xlo (= emb)

    // ---- heads ----
    k_conv_heads<<<(128 * CH + T - 1) / T, T>>>(Wt, Ws, Wf);
    k_pack_bias<<<1, 65>>>(bt, bs, bf);
    k_mma_gemm<<<dim3(MTILES, 2), 256, SM_TOTAL>>>(Xhi, Xlo, Whi, Wlo, nullptr, nullptr,
                                                   NN, 65, 1, 1,
                                                   out, out + (size_t)NN * 30,
                                                   out + (size_t)NN * 50);

    // author head P=2000 (padded 2048 -> 32 n-tiles of 64, split 4 ways)
    k_conv_w<<<(2048 * CH + T - 1) / T, T>>>(Wa, 2000, 2048);
    k_mma_gemm<<<dim3(MTILES, 4), 256, SM_TOTAL>>>(Xhi, Xlo, Whi, Wlo, ba,
                                                   out + (size_t)NN * 65,
                                                   NN, 2000, 8, 0, nullptr, nullptr, nullptr);
}

// round 13
// speedup vs baseline: 2.9216x; 1.5079x over previous
#include <cuda_runtime.h>
#include <cuda_bf16.h>
#include <cstdint>

#define NN 50000
#define NE 800000
#define CH 128
#define NPAD 50048            // 391 * 128
#define MTILES 391
#define WROWS 2432            // W1(128) | W2(128) | heads(128) | Wa(2048)

// ---------------- scratch (no allocations allowed) ----------------
__device__ float g_dinv[NN];
__device__ int   g_cnt[NN];            // starts 0; k_scan re-zeroes after use
__device__ int   g_rowstart[NN + 1];
__device__ int   g_cursor[NN];
__device__ int   g_ecol[NE];
__device__ float g_enorm[NE];
__device__ float g_bufA[(size_t)NN * CH];
__device__ __nv_bfloat16 g_Xhi[(size_t)NPAD * CH];
__device__ __nv_bfloat16 g_Xlo[(size_t)NPAD * CH];
__device__ __nv_bfloat16 g_Whi[(size_t)WROWS * CH];
__device__ __nv_bfloat16 g_Wlo[(size_t)WROWS * CH];
__device__ float g_hbias[65];
__device__ int   g_is64;

// ================= helpers =================
__device__ __forceinline__ uint32_t smem_u32(const void* p) {
    uint32_t a;
    asm("{ .reg .u64 t; cvta.to.shared.u64 t, %1; cvt.u32.u64 %0, t; }" : "=r"(a) : "l"(p));
    return a;
}
__device__ __forceinline__ void ldmat_x4(uint32_t* r, uint32_t addr) {
    asm volatile("ldmatrix.sync.aligned.m8n8.x4.shared.b16 {%0,%1,%2,%3}, [%4];"
        : "=r"(r[0]), "=r"(r[1]), "=r"(r[2]), "=r"(r[3]) : "r"(addr));
}
__device__ __forceinline__ void mma16816(float* d, const uint32_t* a, const uint32_t* b) {
    asm volatile("mma.sync.aligned.m16n8k16.row.col.f32.bf16.bf16.f32 "
        "{%0,%1,%2,%3}, {%4,%5,%6,%7}, {%8,%9}, {%0,%1,%2,%3};"
        : "+f"(d[0]), "+f"(d[1]), "+f"(d[2]), "+f"(d[3])
        : "r"(a[0]), "r"(a[1]), "r"(a[2]), "r"(a[3]), "r"(b[0]), "r"(b[1]));
}
__device__ __forceinline__ void split_store(float v, __nv_bfloat16* hi, __nv_bfloat16* lo) {
    __nv_bfloat16 h = __float2bfloat16(v);
    *hi = h;
    *lo = __float2bfloat16(v - __bfloat162float(h));
}

// ---------------- edge-index dtype sniff ----------------
__global__ void k_detect(const int* __restrict__ ei32) {
    int z = 0;
    for (int i = 1; i < 256; i += 2)
        if (ei32[i] == 0) z++;
    g_is64 = (z > 64) ? 1 : 0;
}
__device__ __forceinline__ int edge_at(const void* __restrict__ ei, int pos) {
    if (g_is64) return (int)((const long long*)ei)[pos];
    return ((const int*)ei)[pos];
}

// ---------------- fused prep: feat split | weight split | degree count | bias pack ----
// grid covers NPAD*CH/4 = 1,601,536 threads; other tasks are strict subsets.
__global__ void k_prep(const float* __restrict__ x,
                       const float* __restrict__ W1, const float* __restrict__ W2,
                       const float* __restrict__ Wt, const float* __restrict__ Ws,
                       const float* __restrict__ Wf, const float* __restrict__ Wa,
                       const float* __restrict__ bt, const float* __restrict__ bs,
                       const float* __restrict__ bf, const void* __restrict__ ei) {
    int id = blockIdx.x * blockDim.x + threadIdx.x;

    // --- task 1: feature fp32 -> bf16 hi/lo (incl. zero pad rows) ---
    if (id < NPAD * CH / 4) {
        int row = id >> 5;
        float4 v = make_float4(0.f, 0.f, 0.f, 0.f);
        if (row < NN) v = ((const float4*)x)[id];
        __nv_bfloat16 h0 = __float2bfloat16(v.x), h1 = __float2bfloat16(v.y);
        __nv_bfloat16 h2 = __float2bfloat16(v.z), h3 = __float2bfloat16(v.w);
        __nv_bfloat162 hA(h0, h1), hB(h2, h3);
        __nv_bfloat162 lA(__float2bfloat16(v.x - __bfloat162float(h0)),
                          __float2bfloat16(v.y - __bfloat162float(h1)));
        __nv_bfloat162 lB(__float2bfloat16(v.z - __bfloat162float(h2)),
                          __float2bfloat16(v.w - __bfloat162float(h3)));
        ((__nv_bfloat162*)g_Xhi)[id * 2] = hA;
        ((__nv_bfloat162*)g_Xhi)[id * 2 + 1] = hB;
        ((__nv_bfloat162*)g_Xlo)[id * 2] = lA;
        ((__nv_bfloat162*)g_Xlo)[id * 2 + 1] = lB;
    }

    // --- task 2: all weights -> transposed [WROWS x 128] hi/lo ---
    if (id < WROWS * CH) {
        int n = id >> 7, k = id & 127;
        float v = 0.f;
        if (n < 128)       v = W1[(size_t)k * 128 + n];
        else if (n < 256)  v = W2[(size_t)k * 128 + (n - 128)];
        else if (n < 384) {
            int m = n - 256;
            if (m < 30)      v = Wt[(size_t)k * 30 + m];
            else if (m < 50) v = Ws[(size_t)k * 20 + (m - 30)];
            else if (m < 65) v = Wf[(size_t)k * 15 + (m - 50)];
        } else {
            int m = n - 384;
            if (m < 2000) v = Wa[(size_t)k * 2000 + m];
        }
        split_store(v, &g_Whi[id], &g_Wlo[id]);
    }

    // --- task 3: degree count ---
    if (id < NE) atomicAdd(&g_cnt[edge_at(ei, id)], 1);

    // --- task 4: packed small-head bias ---
    if (id < 30)      g_hbias[id] = bt[id];
    else if (id < 50) g_hbias[id] = bs[id - 30];
    else if (id < 65) g_hbias[id] = bf[id - 50];
}

// ---------------- scan (+dinv, +cnt clear) ----------------
__global__ void k_scan() {
    __shared__ int swarp[32];
    __shared__ int s_carry;
    int tid = threadIdx.x, lane = tid & 31, wid = tid >> 5;
    if (tid == 0) s_carry = 0;
    __syncthreads();
    for (int base = 0; base < NN; base += 1024) {
        int i = base + tid;
        int v = 0;
        if (i < NN) {
            v = g_cnt[i];
            g_dinv[i] = rsqrtf((float)(v + 1));
            g_cnt[i] = 0;                       // restore invariant for next call
        }
        int incl = v;
        #pragma unroll
        for (int d = 1; d < 32; d <<= 1) {
            int n = __shfl_up_sync(0xffffffffu, incl, d);
            if (lane >= d) incl += n;
        }
        if (lane == 31) swarp[wid] = incl;
        __syncthreads();
        if (wid == 0) {
            int wv = swarp[lane];
            int wincl = wv;
            #pragma unroll
            for (int d = 1; d < 32; d <<= 1) {
                int n = __shfl_up_sync(0xffffffffu, wincl, d);
                if (lane >= d) wincl += n;
            }
            swarp[lane] = wincl - wv;
        }
        __syncthreads();
        int excl = s_carry + swarp[wid] + incl - v;
        if (i < NN) { g_rowstart[i] = excl; g_cursor[i] = excl; }
        __syncthreads();
        if (tid == 1023) s_carry = excl + v;
        __syncthreads();
    }
    if (threadIdx.x == 0) g_rowstart[NN] = s_carry;
}

__global__ void k_fill(const void* __restrict__ ei) {
    int e = blockIdx.x * blockDim.x + threadIdx.x;
    if (e >= NE) return;
    int r = edge_at(ei, e);
    int c = edge_at(ei, NE + e);
    int pos = atomicAdd(&g_cursor[r], 1);
    g_ecol[pos] = c;
    g_enorm[pos] = g_dinv[r] * g_dinv[c];
}

// ---------------- CSR gather aggregation (fused: self + bias + relu + bf16 split) ----
__global__ __launch_bounds__(256) void k_agg_csr(const float* __restrict__ hin,
                                                 const float* __restrict__ bias, int relu) {
    int node = blockIdx.x * 8 + (threadIdx.x >> 5);
    if (node >= NN) return;
    int lane = threadIdx.x & 31;
    float d = g_dinv[node];
    float dd = d * d;
    float4 acc = ((const float4*)(hin + (size_t)node * CH))[lane];
    acc.x *= dd; acc.y *= dd; acc.z *= dd; acc.w *= dd;

    int s = g_rowstart[node], e = g_rowstart[node + 1];
    int j = s;
    for (; j + 4 <= e; j += 4) {
        int   c0 = g_ecol[j],     c1 = g_ecol[j + 1];
        int   c2 = g_ecol[j + 2], c3 = g_ecol[j + 3];
        float w0 = g_enorm[j],    w1 = g_enorm[j + 1];
        float w2 = g_enorm[j + 2], w3 = g_enorm[j + 3];
        float4 v0 = ((const float4*)(hin + (size_t)c0 * CH))[lane];
        float4 v1 = ((const float4*)(hin + (size_t)c1 * CH))[lane];
        float4 v2 = ((const float4*)(hin + (size_t)c2 * CH))[lane];
        float4 v3 = ((const float4*)(hin + (size_t)c3 * CH))[lane];
        acc.x += v0.x * w0 + v1.x * w1 + v2.x * w2 + v3.x * w3;
        acc.y += v0.y * w0 + v1.y * w1 + v2.y * w2 + v3.y * w3;
        acc.z += v0.z * w0 + v1.z * w1 + v2.z * w2 + v3.z * w3;
        acc.w += v0.w * w0 + v1.w * w1 + v2.w * w2 + v3.w * w3;
    }
    for (; j < e; ++j) {
        int c0 = g_ecol[j];
        float w0 = g_enorm[j];
        float4 v0 = ((const float4*)(hin + (size_t)c0 * CH))[lane];
        acc.x += v0.x * w0; acc.y += v0.y * w0;
        acc.z += v0.z * w0; acc.w += v0.w * w0;
    }

    float4 b = ((const float4*)bias)[lane];
    acc.x += b.x; acc.y += b.y; acc.z += b.z; acc.w += b.w;
    if (relu) {
        acc.x = fmaxf(acc.x, 0.f); acc.y = fmaxf(acc.y, 0.f);
        acc.z = fmaxf(acc.z, 0.f); acc.w = fmaxf(acc.w, 0.f);
    }
    __nv_bfloat16 h0 = __float2bfloat16(acc.x), h1 = __float2bfloat16(acc.y);
    __nv_bfloat16 h2 = __float2bfloat16(acc.z), h3 = __float2bfloat16(acc.w);
    __nv_bfloat162 hA(h0, h1), hB(h2, h3);
    __nv_bfloat162 lA(__float2bfloat16(acc.x - __bfloat162float(h0)),
                      __float2bfloat16(acc.y - __bfloat162float(h1)));
    __nv_bfloat162 lB(__float2bfloat16(acc.z - __bfloat162float(h2)),
                      __float2bfloat16(acc.w - __bfloat162float(h3)));
    size_t o = (size_t)node * 64 + lane * 2;
    ((__nv_bfloat162*)g_Xhi)[o]     = hA;
    ((__nv_bfloat162*)g_Xhi)[o + 1] = hB;
    ((__nv_bfloat162*)g_Xlo)[o]     = lA;
    ((__nv_bfloat162*)g_Xlo)[o + 1] = lB;
}

// ---------------- mma.sync bf16-split GEMM ----------------
// C[M x P] = A[M x 128] @ W[128 x P] (+bias), A/W pre-split into bf16 hi/lo.
// BM=128, BN=64, K=128 fully staged. 256 threads = 8 warps, warp tile 32x32.
#define SM_AH 0
#define SM_AL 32768
#define SM_BH 65536
#define SM_BL (65536 + 16384)
#define SM_TOTAL (65536 + 32768)

__device__ __forceinline__ uint32_t tile_off(int row, int chunk) {
    return (uint32_t)row * 256u + (uint32_t)((chunk ^ (row & 7)) << 4);
}

__global__ __launch_bounds__(256, 2) void k_mma_gemm(
    const __nv_bfloat16* __restrict__ Ah, const __nv_bfloat16* __restrict__ Al,
    const __nv_bfloat16* __restrict__ Bh, const __nv_bfloat16* __restrict__ Bl,
    const float* __restrict__ bias, float* __restrict__ C,
    int M, int P, int ntPerY, int mode,
    float* __restrict__ o1, float* __restrict__ o2, float* __restrict__ o3)
{
    extern __shared__ __align__(1024) char smem[];
    uint32_t sb = smem_u32(smem);
    int tid = threadIdx.x;
    int lane = tid & 31;
    int wid = tid >> 5;
    int wm = wid & 3;
    int wn = wid >> 2;
    int g = lane >> 3, i8 = lane & 7;
    int mBase = blockIdx.x * 128;
    int ntBegin = blockIdx.y * ntPerY;

    #pragma unroll
    for (int it = 0; it < 8; ++it) {
        int id = tid + it * 256;
        int r = id >> 4;
        int c = id & 15;
        uint32_t so = tile_off(r, c);
        *(uint4*)(smem + SM_AH + so) = ((const uint4*)(Ah + (size_t)(mBase + r) * CH))[c];
        *(uint4*)(smem + SM_AL + so) = ((const uint4*)(Al + (size_t)(mBase + r) * CH))[c];
    }

    for (int t = 0; t < ntPerY; ++t) {
        int nt = ntBegin + t;
        int colBase = nt * 64;
        __syncthreads();
        #pragma unroll
        for (int it = 0; it < 4; ++it) {
            int id = tid + it * 256;
            int r = id >> 4;
            int c = id & 15;
            uint32_t so = tile_off(r, c);
            *(uint4*)(smem + SM_BH + so) = ((const uint4*)(Bh + (size_t)(colBase + r) * CH))[c];
            *(uint4*)(smem + SM_BL + so) = ((const uint4*)(Bl + (size_t)(colBase + r) * CH))[c];
        }
        __syncthreads();

        float acc[2][4][4];
        #pragma unroll
        for (int a = 0; a < 2; ++a)
            #pragma unroll
            for (int b = 0; b < 4; ++b)
                #pragma unroll
                for (int c = 0; c < 4; ++c) acc[a][b][c] = 0.f;

        #pragma unroll
        for (int ks = 0; ks < 8; ++ks) {
            int c0 = ks * 2;
            uint32_t a_h[2][4], a_l[2][4], b_h[2][4], b_l[2][4];
            #pragma unroll
            for (int mb = 0; mb < 2; ++mb) {
                int row = wm * 32 + mb * 16 + (g & 1) * 8 + i8;
                int ch = c0 + (g >> 1);
                uint32_t off = tile_off(row, ch);
                ldmat_x4(a_h[mb], sb + SM_AH + off);
                ldmat_x4(a_l[mb], sb + SM_AL + off);
            }
            #pragma unroll
            for (int np = 0; np < 2; ++np) {
                int rn = wn * 32 + np * 16 + (g >> 1) * 8 + i8;
                int ch = c0 + (g & 1);
                uint32_t off = tile_off(rn, ch);
                ldmat_x4(b_h[np], sb + SM_BH + off);
                ldmat_x4(b_l[np], sb + SM_BL + off);
            }
            #pragma unroll
            for (int mb = 0; mb < 2; ++mb)
                #pragma unroll
                for (int nb = 0; nb < 4; ++nb) {
                    float* ac = acc[mb][nb];
                    const uint32_t* bh = &b_h[nb >> 1][(nb & 1) * 2];
                    const uint32_t* bl = &b_l[nb >> 1][(nb & 1) * 2];
                    mma16816(ac, a_h[mb], bh);
                    mma16816(ac, a_h[mb], bl);
                    mma16816(ac, a_l[mb], bh);
                }
        }

        #pragma unroll
        for (int mb = 0; mb < 2; ++mb) {
            int gr = mBase + wm * 32 + mb * 16 + (lane >> 2);
            #pragma unroll
            for (int nb = 0; nb < 4; ++nb) {
                int gc = colBase + wn * 32 + nb * 8 + (lane & 3) * 2;
                float* ac = acc[mb][nb];
                if (mode == 0) {
                    if (gc < P) {
                        float bx = bias ? __ldg(bias + gc) : 0.f;
                        float by = bias ? __ldg(bias + gc + 1) : 0.f;
                        if (gr < M)
                            *(float2*)(C + (size_t)gr * P + gc) =
                                make_float2(ac[0] + bx, ac[1] + by);
                        if (gr + 8 < M)
                            *(float2*)(C + (size_t)(gr + 8) * P + gc) =
                                make_float2(ac[2] + bx, ac[3] + by);
                    }
                } else {
                    #pragma unroll
                    for (int e = 0; e < 4; ++e) {
                        int c = gc + (e & 1);
                        int r = gr + (e >> 1) * 8;
                        if (c < 65 && r < M) {
                            float v = ac[e] + g_hbias[c];
                            if (c < 30)      o1[(size_t)r * 30 + c] = v;
                            else if (c < 50) o2[(size_t)r * 20 + (c - 30)] = v;
                            else             o3[(size_t)r * 15 + (c - 50)] = v;
                        }
                    }
                }
            }
        }
    }
}

// ---------------- launch ----------------
extern "C" void kernel_launch(void* const* d_in, const int* in_sizes, int n_in,
                              void* d_out, int out_size) {
    const float* x  = (const float*)d_in[0];
    const void*  ei = d_in[1];
    const float* W1 = (const float*)d_in[2];
    const float* b1 = (const float*)d_in[3];
    const float* W2 = (const float*)d_in[4];
    const float* b2 = (const float*)d_in[5];
    const float* Wt = (const float*)d_in[6];
    const float* bt = (const float*)d_in[7];
    const float* Ws = (const float*)d_in[8];
    const float* bs = (const float*)d_in[9];
    const float* Wf = (const float*)d_in[10];
    const float* bf = (const float*)d_in[11];
    const float* Wa = (const float*)d_in[12];
    const float* ba = (const float*)d_in[13];
    float* out = (float*)d_out;

    float *bufA;
    __nv_bfloat16 *Xhi, *Xlo, *Whi, *Wlo;
    cudaGetSymbolAddress((void**)&bufA, g_bufA);
    cudaGetSymbolAddress((void**)&Xhi, g_Xhi);
    cudaGetSymbolAddress((void**)&Xlo, g_Xlo);
    cudaGetSymbolAddress((void**)&Whi, g_Whi);
    cudaGetSymbolAddress((void**)&Wlo, g_Wlo);

    cudaFuncSetAttribute(k_mma_gemm, cudaFuncAttributeMaxDynamicSharedMemorySize, SM_TOTAL);

    const int T = 256;

    // ---- prep + CSR build (4 launches) ----
    k_detect<<<1, 1>>>((const int*)ei);
    k_prep<<<(NPAD * CH / 4 + T - 1) / T, T>>>(x, W1, W2, Wt, Ws, Wf, Wa, bt, bs, bf, ei);
    k_scan<<<1, 1024>>>();
    k_fill<<<(NE + T - 1) / T, T>>>(ei);

    // ---- layer 1 ----
    k_mma_gemm<<<dim3(MTILES, 2), 256, SM_TOTAL>>>(Xhi, Xlo, Whi, Wlo, nullptr, bufA,
                                                   NN, CH, 1, 0, nullptr, nullptr, nullptr);
    k_agg_csr<<<(NN + 7) / 8, 256>>>(bufA, b1, 1);

    // ---- layer 2 ----
    k_mma_gemm<<<dim3(MTILES, 2), 256, SM_TOTAL>>>(Xhi, Xlo,
                                                   Whi + (size_t)128 * CH, Wlo + (size_t)128 * CH,
                                                   nullptr, bufA,
                                                   NN, CH, 1, 0, nullptr, nullptr, nullptr);
    k_agg_csr<<<(NN + 7) / 8, 256>>>(bufA, b2, 0);

    // ---- small heads (type 30 | school 20 | time 15) ----
    k_mma_gemm<<<dim3(MTILES, 2), 256, SM_TOTAL>>>(Xhi, Xlo,
                                                   Whi + (size_t)256 * CH, Wlo + (size_t)256 * CH,
                                                   nullptr, nullptr,
                                                   NN, 65, 1, 1,
                                                   out, out + (size_t)NN * 30,
                                                   out + (size_t)NN * 50);

    // ---- author head P=2000 (padded 2048 -> 32 n-tiles of 64, split 4 ways) ----
    k_mma_gemm<<<dim3(MTILES, 4), 256, SM_TOTAL>>>(Xhi, Xlo,
                                                   Whi + (size_t)384 * CH, Wlo + (size_t)384 * CH,
                                                   ba, out + (size_t)NN * 65,
                                                   NN, 2000, 8, 0, nullptr, nullptr, nullptr);
}